// round 1
// baseline (speedup 1.0000x reference)
#include <cuda_runtime.h>
#include <math.h>

#define Bn 128
#define Tn 512
#define Dn 256
#define Vn 4096
#define Sn 512

// Scratch ping-pong buffers (no cudaMalloc allowed): 67 MB each.
__device__ float g_bufA[Bn * Tn * Dn];
__device__ float g_bufB[Bn * Tn * Dn];

// ---------------------------------------------------------------------------
// GEMM (NT):  C[M][N] = A'[M][256] * Bw[N][256]^T  (+ bias1[n]+bias2[n])
// A' row m = A[ids[m]] if ids != nullptr else A[m].
// BM=BN=64, BK=32, 256 threads, 4x4 micro-tile per thread.
// ---------------------------------------------------------------------------
__global__ __launch_bounds__(256) void gemm_nt(
    const float* __restrict__ A, const int* __restrict__ ids,
    const float* __restrict__ Bw, const float* __restrict__ bias1,
    const float* __restrict__ bias2, float* __restrict__ C, int N)
{
    const int K = 256;
    __shared__ float As[32 * 68];   // [k][m], padded to 68
    __shared__ float Bs[32 * 68];   // [k][n], padded to 68

    int tid = threadIdx.x;
    int bm0 = blockIdx.y * 64;
    int bn0 = blockIdx.x * 64;
    int tx = tid & 15;        // n direction
    int ty = tid >> 4;        // m direction

    int lrow = tid >> 3;          // 0..31
    int lcol = (tid & 7) * 4;     // 0,4,...,28

    // Hoist A/B row pointers (gather resolved once).
    const float* arow[2];
    const float* brow[2];
#pragma unroll
    for (int r = 0; r < 2; r++) {
        int m = bm0 + r * 32 + lrow;
        int src = ids ? ids[m] : m;
        arow[r] = A + (size_t)src * K;
        brow[r] = Bw + (size_t)(bn0 + r * 32 + lrow) * K;
    }

    float acc[4][4];
#pragma unroll
    for (int i = 0; i < 4; i++)
#pragma unroll
        for (int j = 0; j < 4; j++) acc[i][j] = 0.f;

    for (int k0 = 0; k0 < K; k0 += 32) {
        __syncthreads();
#pragma unroll
        for (int r = 0; r < 2; r++) {
            int row = r * 32 + lrow;
            float4 va = *(const float4*)(arow[r] + k0 + lcol);
            As[(lcol + 0) * 68 + row] = va.x;
            As[(lcol + 1) * 68 + row] = va.y;
            As[(lcol + 2) * 68 + row] = va.z;
            As[(lcol + 3) * 68 + row] = va.w;
            float4 vb = *(const float4*)(brow[r] + k0 + lcol);
            Bs[(lcol + 0) * 68 + row] = vb.x;
            Bs[(lcol + 1) * 68 + row] = vb.y;
            Bs[(lcol + 2) * 68 + row] = vb.z;
            Bs[(lcol + 3) * 68 + row] = vb.w;
        }
        __syncthreads();

#pragma unroll
        for (int k = 0; k < 32; k++) {
            float4 a4 = *(const float4*)&As[k * 68 + ty * 4];
            float4 b4 = *(const float4*)&Bs[k * 68 + tx * 4];
            float av[4] = {a4.x, a4.y, a4.z, a4.w};
            float bv[4] = {b4.x, b4.y, b4.z, b4.w};
#pragma unroll
            for (int i = 0; i < 4; i++)
#pragma unroll
                for (int j = 0; j < 4; j++)
                    acc[i][j] += av[i] * bv[j];
        }
    }

    float bb[4] = {0.f, 0.f, 0.f, 0.f};
    if (bias1) {
#pragma unroll
        for (int j = 0; j < 4; j++) {
            int n = bn0 + tx * 4 + j;
            bb[j] = bias1[n] + bias2[n];
        }
    }
#pragma unroll
    for (int i = 0; i < 4; i++) {
        int m = bm0 + ty * 4 + i;
        float4 o;
        o.x = acc[i][0] + bb[0];
        o.y = acc[i][1] + bb[1];
        o.z = acc[i][2] + bb[2];
        o.w = acc[i][3] + bb[3];
        *(float4*)&C[(size_t)m * N + bn0 + tx * 4] = o;
    }
}

// ---------------------------------------------------------------------------
// Recurrence: one CTA per batch row, 512 sequential steps in-CTA.
//   h_t = tanh(pre_t + W_hh @ h_{t-1})
// W rows 0..127 in shared (pitch 257, conflict-free); rows 128..255 held in
// registers (128 per thread, 256 threads). Each thread computes half-K
// partials for two outputs (one shared-row, one register-row); halves are
// combined through a small shared buffer.
// ---------------------------------------------------------------------------
extern __shared__ float smem[];

__global__ void __launch_bounds__(256, 1) rnn_recur(
    const float* __restrict__ pre,   // [B][T][D]
    const float* __restrict__ Whh,   // [D][D]
    float* __restrict__ hout)        // [B][T][D]
{
    float* Wsh  = smem;                 // 128 * 257 floats
    float* hbuf = smem + 128 * 257;     // 256
    float* part = hbuf + 256;           // 256

    int b  = blockIdx.x;
    int t  = threadIdx.x;
    int j  = t & 127;
    int hf = t >> 7;
    int base = hf * 128;

    // Shared half of W (rows 0..127), padded pitch 257 for conflict-free reads
    for (int i = t; i < 128 * 256; i += 256) {
        int r = i >> 8, c = i & 255;
        Wsh[r * 257 + c] = Whh[r * 256 + c];
    }
    // Register half of W (rows 128..255): thread (j,hf) holds
    // W[128+j][hf*128 .. hf*128+127]
    float wr[128];
    {
        const float* wrow = Whh + (size_t)(128 + j) * 256 + base;
#pragma unroll
        for (int d = 0; d < 128; d++) wr[d] = wrow[d];
    }

    hbuf[t] = 0.f;
    __syncthreads();

    const float* prow = pre  + ((size_t)b * Tn) * Dn;
    float*       orow = hout + ((size_t)b * Tn) * Dn;

#pragma unroll 1
    for (int step = 0; step < Tn; step++) {
        float ps0 = 0.f, ps1 = 0.f, pr0 = 0.f, pr1 = 0.f;
        const float* wsrow = Wsh + j * 257 + base;
#pragma unroll
        for (int d4 = 0; d4 < 32; d4++) {
            float4 hv = *(const float4*)&hbuf[base + d4 * 4];
            ps0 += wsrow[d4 * 4 + 0] * hv.x;
            ps1 += wsrow[d4 * 4 + 1] * hv.y;
            ps0 += wsrow[d4 * 4 + 2] * hv.z;
            ps1 += wsrow[d4 * 4 + 3] * hv.w;
            pr0 += wr[d4 * 4 + 0] * hv.x;
            pr1 += wr[d4 * 4 + 1] * hv.y;
            pr0 += wr[d4 * 4 + 2] * hv.z;
            pr1 += wr[d4 * 4 + 3] * hv.w;
        }
        float psh = ps0 + ps1;
        float prg = pr0 + pr1;

        if (hf) {
            part[j]       = psh;
            part[128 + j] = prg;
        }
        __syncthreads();   // also guarantees all hbuf reads are done
        if (!hf) {
            float v0 = tanhf(prow[j]       + psh + part[j]);
            float v1 = tanhf(prow[128 + j] + prg + part[128 + j]);
            hbuf[j]       = v0;
            hbuf[128 + j] = v1;
            orow[j]       = v0;
            orow[128 + j] = v1;
        }
        __syncthreads();
        prow += Dn;
        orow += Dn;
    }
}

// ---------------------------------------------------------------------------
extern "C" void kernel_launch(void* const* d_in, const int* in_sizes, int n_in,
                              void* d_out, int out_size)
{
    (void)in_sizes; (void)n_in; (void)out_size;

    const int*   ids   = (const int*)  d_in[0];
    const float* emb   = (const float*)d_in[1];
    const float* Wih0  = (const float*)d_in[2];
    const float* Whh0  = (const float*)d_in[3];
    const float* bih0  = (const float*)d_in[4];
    const float* bhh0  = (const float*)d_in[5];
    const float* Wih1  = (const float*)d_in[6];
    const float* Whh1  = (const float*)d_in[7];
    const float* bih1  = (const float*)d_in[8];
    const float* bhh1  = (const float*)d_in[9];
    const float* Whead = (const float*)d_in[10];
    float* out = (float*)d_out;

    float *bufA, *bufB;
    cudaGetSymbolAddress((void**)&bufA, g_bufA);
    cudaGetSymbolAddress((void**)&bufB, g_bufB);

    const int recur_smem = (128 * 257 + 256 + 256) * 4;  // 133632 B
    cudaFuncSetAttribute(rnn_recur, cudaFuncAttributeMaxDynamicSharedMemorySize,
                         recur_smem);

    const int M = Bn * Tn;
    dim3 thr(256);

    // pre0 = emb[ids] @ W_ih0^T + (b_ih0 + b_hh0)
    gemm_nt<<<dim3(Dn / 64, M / 64), thr>>>(emb, ids, Wih0, bih0, bhh0, bufA, Dn);
    // h1 recurrence
    rnn_recur<<<Bn, 256, recur_smem>>>(bufA, Whh0, bufB);
    // pre1 = h1 @ W_ih1^T + (b_ih1 + b_hh1)
    gemm_nt<<<dim3(Dn / 64, M / 64), thr>>>(bufB, nullptr, Wih1, bih1, bhh1, bufA, Dn);
    // h2 recurrence
    rnn_recur<<<Bn, 256, recur_smem>>>(bufA, Whh1, bufB);
    // logits = h2 @ W_head^T  (no bias)
    gemm_nt<<<dim3(Sn / 64, M / 64), thr>>>(bufB, nullptr, Whead, nullptr, nullptr,
                                            out, Sn);
}

// round 2
// speedup vs baseline: 1.1827x; 1.1827x over previous
#include <cuda_runtime.h>
#include <math.h>

#define Bn 128
#define Tn 512
#define Dn 256
#define Vn 4096
#define Sn 512

// Scratch ping-pong buffers (no cudaMalloc allowed): 67 MB each.
__device__ float g_bufA[Bn * Tn * Dn];
__device__ float g_bufB[Bn * Tn * Dn];

// ---------------------------------------------------------------------------
// GEMM (NT):  C[M][N] = A'[M][256] * Bw[N][256]^T  (+ bias1[n]+bias2[n])
// A' row m = A[ids[m]] if ids != nullptr else A[m].
// BM=BN=64, BK=32, 256 threads, 4x4 micro-tile per thread. Near fp32 FMA floor.
// ---------------------------------------------------------------------------
__global__ __launch_bounds__(256) void gemm_nt(
    const float* __restrict__ A, const int* __restrict__ ids,
    const float* __restrict__ Bw, const float* __restrict__ bias1,
    const float* __restrict__ bias2, float* __restrict__ C, int N)
{
    const int K = 256;
    __shared__ float As[32 * 68];   // [k][m], padded to 68
    __shared__ float Bs[32 * 68];   // [k][n], padded to 68

    int tid = threadIdx.x;
    int bm0 = blockIdx.y * 64;
    int bn0 = blockIdx.x * 64;
    int tx = tid & 15;        // n direction
    int ty = tid >> 4;        // m direction

    int lrow = tid >> 3;          // 0..31
    int lcol = (tid & 7) * 4;     // 0,4,...,28

    const float* arow[2];
    const float* brow[2];
#pragma unroll
    for (int r = 0; r < 2; r++) {
        int m = bm0 + r * 32 + lrow;
        int src = ids ? ids[m] : m;
        arow[r] = A + (size_t)src * K;
        brow[r] = Bw + (size_t)(bn0 + r * 32 + lrow) * K;
    }

    float acc[4][4];
#pragma unroll
    for (int i = 0; i < 4; i++)
#pragma unroll
        for (int j = 0; j < 4; j++) acc[i][j] = 0.f;

    for (int k0 = 0; k0 < K; k0 += 32) {
        __syncthreads();
#pragma unroll
        for (int r = 0; r < 2; r++) {
            int row = r * 32 + lrow;
            float4 va = *(const float4*)(arow[r] + k0 + lcol);
            As[(lcol + 0) * 68 + row] = va.x;
            As[(lcol + 1) * 68 + row] = va.y;
            As[(lcol + 2) * 68 + row] = va.z;
            As[(lcol + 3) * 68 + row] = va.w;
            float4 vb = *(const float4*)(brow[r] + k0 + lcol);
            Bs[(lcol + 0) * 68 + row] = vb.x;
            Bs[(lcol + 1) * 68 + row] = vb.y;
            Bs[(lcol + 2) * 68 + row] = vb.z;
            Bs[(lcol + 3) * 68 + row] = vb.w;
        }
        __syncthreads();

#pragma unroll
        for (int k = 0; k < 32; k++) {
            float4 a4 = *(const float4*)&As[k * 68 + ty * 4];
            float4 b4 = *(const float4*)&Bs[k * 68 + tx * 4];
            float av[4] = {a4.x, a4.y, a4.z, a4.w};
            float bv[4] = {b4.x, b4.y, b4.z, b4.w};
#pragma unroll
            for (int i = 0; i < 4; i++)
#pragma unroll
                for (int j = 0; j < 4; j++)
                    acc[i][j] += av[i] * bv[j];
        }
    }

    float bb[4] = {0.f, 0.f, 0.f, 0.f};
    if (bias1) {
#pragma unroll
        for (int j = 0; j < 4; j++) {
            int n = bn0 + tx * 4 + j;
            bb[j] = bias1[n] + bias2[n];
        }
    }
#pragma unroll
    for (int i = 0; i < 4; i++) {
        int m = bm0 + ty * 4 + i;
        float4 o;
        o.x = acc[i][0] + bb[0];
        o.y = acc[i][1] + bb[1];
        o.z = acc[i][2] + bb[2];
        o.w = acc[i][3] + bb[3];
        *(float4*)&C[(size_t)m * N + bn0 + tx * 4] = o;
    }
}

// ---------------------------------------------------------------------------
// Recurrence v2: one CTA per batch row, 512 sequential steps in-CTA.
//   h_t = tanh(pre_t + W_hh @ h_{t-1})
// Thread j owns output row j entirely:
//   - W[j][0:192]   in 48 float4 registers   (48K regs / CTA)
//   - W[j][192:256] in smem, pitch 17 float4 (conflict-free LDS.128)
//   - h double-buffered in smem (one __syncthreads per step)
//   - pre prefetched one step ahead
// Step floor: FMA 1024 cyc; crossbar ~1030 cyc (W 512 + h-broadcast 512).
// ---------------------------------------------------------------------------
#define WREG 48   // float4's of W per thread in registers (192 floats)
#define WSMQ 16   // float4's of W per thread in smem      (64 floats)
#define WPITCH4 17  // smem W row pitch in float4 (17 mod 8 = 1 -> conflict-free)

__device__ __forceinline__ float rnn_dot(
    const float4* __restrict__ wr, const float4* __restrict__ wsr,
    const float4* __restrict__ hb)
{
    float a0 = 0.f, a1 = 0.f, a2 = 0.f, a3 = 0.f;
#pragma unroll
    for (int q = 0; q < WREG; q++) {
        float4 h = hb[q];
        float4 w = wr[q];
        a0 = fmaf(w.x, h.x, a0);
        a1 = fmaf(w.y, h.y, a1);
        a2 = fmaf(w.z, h.z, a2);
        a3 = fmaf(w.w, h.w, a3);
    }
#pragma unroll
    for (int q = 0; q < WSMQ; q++) {
        float4 h = hb[WREG + q];
        float4 w = wsr[q];
        a0 = fmaf(w.x, h.x, a0);
        a1 = fmaf(w.y, h.y, a1);
        a2 = fmaf(w.z, h.z, a2);
        a3 = fmaf(w.w, h.w, a3);
    }
    return (a0 + a1) + (a2 + a3);
}

extern __shared__ float smem_r[];

__global__ void __launch_bounds__(256, 1) rnn_recur(
    const float* __restrict__ pre,   // [B][T][D]
    const float* __restrict__ Whh,   // [D][D]
    float* __restrict__ hout)        // [B][T][D]
{
    float4* Wsm = (float4*)smem_r;                    // [256][WPITCH4] float4
    float*  hA  = smem_r + 256 * WPITCH4 * 4;         // 256 floats
    float*  hB  = hA + 256;                           // 256 floats

    int b = blockIdx.x;
    int j = threadIdx.x;

    // Register part of W row j: cols [0,192)
    float4 wr[WREG];
    {
        const float4* wrow = (const float4*)(Whh + (size_t)j * 256);
#pragma unroll
        for (int q = 0; q < WREG; q++) wr[q] = wrow[q];
    }
    // Smem part: all rows' cols [192,256), cooperatively loaded (16 float4/row)
    for (int i = j; i < 256 * WSMQ; i += 256) {
        int r = i >> 4, c = i & 15;
        Wsm[r * WPITCH4 + c] =
            ((const float4*)(Whh + (size_t)r * 256 + WREG * 4))[c];
    }

    hA[j] = 0.f;
    __syncthreads();

    const float* prow = pre  + ((size_t)b * Tn) * Dn;
    float*       orow = hout + ((size_t)b * Tn) * Dn;
    const float4* wsr = Wsm + j * WPITCH4;

    float pcur = prow[j];

#pragma unroll 1
    for (int step = 0; step < Tn; step += 2) {
        // --- sub-step A: read hA, write hB ---
        {
            float pnext = prow[Dn + j];
            float s = rnn_dot(wr, wsr, (const float4*)hA);
            float v = tanhf(pcur + s);
            hB[j]   = v;
            orow[j] = v;
            __syncthreads();
            pcur = pnext;
            prow += Dn;
            orow += Dn;
        }
        // --- sub-step B: read hB, write hA ---
        {
            float pnext = (step + 2 < Tn) ? prow[Dn + j] : 0.f;
            float s = rnn_dot(wr, wsr, (const float4*)hB);
            float v = tanhf(pcur + s);
            hA[j]   = v;
            orow[j] = v;
            __syncthreads();
            pcur = pnext;
            prow += Dn;
            orow += Dn;
        }
    }
}

// ---------------------------------------------------------------------------
extern "C" void kernel_launch(void* const* d_in, const int* in_sizes, int n_in,
                              void* d_out, int out_size)
{
    (void)in_sizes; (void)n_in; (void)out_size;

    const int*   ids   = (const int*)  d_in[0];
    const float* emb   = (const float*)d_in[1];
    const float* Wih0  = (const float*)d_in[2];
    const float* Whh0  = (const float*)d_in[3];
    const float* bih0  = (const float*)d_in[4];
    const float* bhh0  = (const float*)d_in[5];
    const float* Wih1  = (const float*)d_in[6];
    const float* Whh1  = (const float*)d_in[7];
    const float* bih1  = (const float*)d_in[8];
    const float* bhh1  = (const float*)d_in[9];
    const float* Whead = (const float*)d_in[10];
    float* out = (float*)d_out;

    float *bufA, *bufB;
    cudaGetSymbolAddress((void**)&bufA, g_bufA);
    cudaGetSymbolAddress((void**)&bufB, g_bufB);

    const int recur_smem = (256 * WPITCH4 * 4 + 512) * 4;  // 71680 B
    cudaFuncSetAttribute(rnn_recur, cudaFuncAttributeMaxDynamicSharedMemorySize,
                         recur_smem);

    const int M = Bn * Tn;
    dim3 thr(256);

    // pre0 = emb[ids] @ W_ih0^T + (b_ih0 + b_hh0)
    gemm_nt<<<dim3(Dn / 64, M / 64), thr>>>(emb, ids, Wih0, bih0, bhh0, bufA, Dn);
    // h1 recurrence
    rnn_recur<<<Bn, 256, recur_smem>>>(bufA, Whh0, bufB);
    // pre1 = h1 @ W_ih1^T + (b_ih1 + b_hh1)
    gemm_nt<<<dim3(Dn / 64, M / 64), thr>>>(bufB, nullptr, Wih1, bih1, bhh1, bufA, Dn);
    // h2 recurrence
    rnn_recur<<<Bn, 256, recur_smem>>>(bufA, Whh1, bufB);
    // logits = h2 @ W_head^T  (no bias)
    gemm_nt<<<dim3(Sn / 64, M / 64), thr>>>(bufB, nullptr, Whead, nullptr, nullptr,
                                            out, Sn);
}

// round 4
// speedup vs baseline: 1.8007x; 1.5225x over previous
#include <cuda_runtime.h>
#include <cuda_bf16.h>
#include <math.h>
#include <stdint.h>

#define Bn 128
#define Tn 512
#define Dn 256
#define Vn 4096
#define Sn 512

// ---------------------------------------------------------------------------
// Device scratch (no cudaMalloc allowed)
// ---------------------------------------------------------------------------
__device__ float          g_pre[Bn * Tn * Dn];          // fp32 pre-activations
__device__ __nv_bfloat16  g_hH[Bn * Tn * Dn];           // hidden hi
__device__ __nv_bfloat16  g_hL[Bn * Tn * Dn];           // hidden lo
__device__ __nv_bfloat16  g_embH[Vn * Dn], g_embL[Vn * Dn];
__device__ __nv_bfloat16  g_w0H[Dn * Dn],  g_w0L[Dn * Dn];
__device__ __nv_bfloat16  g_w1H[Dn * Dn],  g_w1L[Dn * Dn];
__device__ __nv_bfloat16  g_whH[Sn * Dn],  g_whL[Sn * Dn];

// ---------------------------------------------------------------------------
// mma.sync / ldmatrix helpers (sm_80-era PTX: legal under compute_103)
// ---------------------------------------------------------------------------
__device__ __forceinline__ uint32_t smem_u32(const void* p) {
    uint32_t a;
    asm("{ .reg .u64 t; cvta.to.shared.u64 t, %1; cvt.u32.u64 %0, t; }"
        : "=r"(a) : "l"(p));
    return a;
}
__device__ __forceinline__ void ldsm4(uint32_t r[4], uint32_t addr) {
    asm volatile("ldmatrix.sync.aligned.m8n8.x4.shared.b16 {%0,%1,%2,%3}, [%4];"
                 : "=r"(r[0]), "=r"(r[1]), "=r"(r[2]), "=r"(r[3]) : "r"(addr));
}
__device__ __forceinline__ void mma_bf16(float d[4], const uint32_t a[4],
                                         const uint32_t b[2]) {
    asm volatile(
        "mma.sync.aligned.m16n8k16.row.col.f32.bf16.bf16.f32 "
        "{%0,%1,%2,%3}, {%4,%5,%6,%7}, {%8,%9}, {%0,%1,%2,%3};"
        : "+f"(d[0]), "+f"(d[1]), "+f"(d[2]), "+f"(d[3])
        : "r"(a[0]), "r"(a[1]), "r"(a[2]), "r"(a[3]), "r"(b[0]), "r"(b[1]));
}

// ---------------------------------------------------------------------------
// Tensor-core GEMM:  C[M][N] = (AH+AL)[M][256] * (BH+BL)[N][256]^T (+b1[n]+b2[n])
// bf16 hi/lo split (3 products), fp32 register accumulate.
// CTA = 128 M rows; A (hi+lo, full K) resident in smem; loops N tiles of 128.
// B double-buffered in 32-wide K chunks. 8 warps = 2(m) x 4(n), 64x32 each.
// A rows padded to 528B, B rows to 80B -> conflict-free ldmatrix.
// ---------------------------------------------------------------------------
#define A_PITCH 528
#define B_PITCH 80
#define SM_AH   0
#define SM_AL   (128 * A_PITCH)                 // 67584
#define SM_B    (2 * 128 * A_PITCH)             // 135168; (stage*2+half)*10240
#define B_SEG   (128 * B_PITCH)                 // 10240
#define GEMM_SMEM (SM_B + 4 * B_SEG)            // 176128 B

__global__ __launch_bounds__(256, 1) void gemm_mma(
    const __nv_bfloat16* __restrict__ AH, const __nv_bfloat16* __restrict__ AL,
    const int* __restrict__ ids,
    const __nv_bfloat16* __restrict__ BH, const __nv_bfloat16* __restrict__ BL,
    const float* __restrict__ b1, const float* __restrict__ b2,
    float* __restrict__ C, int N)
{
    extern __shared__ char gsm[];
    const uint32_t sb = smem_u32(gsm);

    const int tid = threadIdx.x;
    const int wid = tid >> 5, lane = tid & 31;
    const int warp_m = wid >> 2;       // 0..1
    const int warp_n = wid & 3;        // 0..3
    const int m0 = blockIdx.x * 128;

    // ---- Load A tile (128 x 256, hi+lo) resident; gather via ids if set ----
#pragma unroll 4
    for (int i = tid; i < 4096; i += 256) {       // 4096 uint4 per half
        int row = i >> 5, seg = i & 31;
        int src = ids ? __ldg(ids + m0 + row) : (m0 + row);
        const uint4* gh = (const uint4*)(AH + (size_t)src * 256 + seg * 8);
        const uint4* gl = (const uint4*)(AL + (size_t)src * 256 + seg * 8);
        *(uint4*)(gsm + SM_AH + row * A_PITCH + seg * 16) = *gh;
        *(uint4*)(gsm + SM_AL + row * A_PITCH + seg * 16) = *gl;
    }

    // ---- Per-lane ldmatrix addresses ----
    // A x4: lanes 0-15 -> tile rows 0-15 (k lo-half), 16-31 -> rows 0-15 (k hi)
    const int aRow = warp_m * 64 + (lane & 15);
    const uint32_t aOff = (uint32_t)aRow * A_PITCH + ((lane >> 4) * 8) * 2;
    const uint32_t aBaseH = sb + SM_AH + aOff;
    const uint32_t aBaseL = sb + SM_AL + aOff;
    // B x4: lanes 0-7: j-pair tile0 k0-7; 8-15: tile0 k8-15; 16-23: tile1 k0-7; ...
    const int bN = warp_n * 32 + (lane & 7) + ((lane >> 4) << 3);
    const uint32_t bOff = (uint32_t)bN * B_PITCH + ((lane >> 3) & 1) * 16;
    const uint32_t bBase = sb + SM_B + bOff;

    // ---- B chunk loader mapping (per thread: 2 rows' worth -> 64B) ----
    const int lrow = tid >> 1;               // 0..127
    const int lseg = (tid & 1) * 2;          // uint4 seg 0 or 2 (of 4)

    const int nTiles = N >> 7;
#pragma unroll 1
    for (int nt = 0; nt < nTiles; nt++) {
        const int n0 = nt << 7;

        float acc[4][4][4];
#pragma unroll
        for (int i = 0; i < 4; i++)
#pragma unroll
            for (int j = 0; j < 4; j++)
#pragma unroll
                for (int r = 0; r < 4; r++) acc[i][j][r] = 0.f;

        __syncthreads();   // A resident ready (nt=0) / prev stage reads done

        // preload chunk 0 -> stage 0
        {
            const __nv_bfloat16* gh = BH + (size_t)(n0 + lrow) * 256 + lseg * 8;
            const __nv_bfloat16* gl = BL + (size_t)(n0 + lrow) * 256 + lseg * 8;
            uint4 h0 = *(const uint4*)gh, h1 = *(const uint4*)(gh + 8);
            uint4 l0 = *(const uint4*)gl, l1 = *(const uint4*)(gl + 8);
            char* dh = gsm + SM_B + 0 * B_SEG + lrow * B_PITCH + lseg * 16;
            char* dl = gsm + SM_B + 1 * B_SEG + lrow * B_PITCH + lseg * 16;
            *(uint4*)dh = h0; *(uint4*)(dh + 16) = h1;
            *(uint4*)dl = l0; *(uint4*)(dl + 16) = l1;
        }
        __syncthreads();

#pragma unroll 1
        for (int kc = 0; kc < 8; kc++) {
            const int s = kc & 1;

            // prefetch next chunk into registers
            uint4 h0, h1, l0, l1;
            if (kc < 7) {
                const __nv_bfloat16* gh =
                    BH + (size_t)(n0 + lrow) * 256 + (kc + 1) * 32 + lseg * 8;
                const __nv_bfloat16* gl =
                    BL + (size_t)(n0 + lrow) * 256 + (kc + 1) * 32 + lseg * 8;
                h0 = *(const uint4*)gh; h1 = *(const uint4*)(gh + 8);
                l0 = *(const uint4*)gl; l1 = *(const uint4*)(gl + 8);
            }

            // MMA over this chunk (two k16 steps)
#pragma unroll
            for (int kk = 0; kk < 2; kk++) {
                const uint32_t aK = (uint32_t)(kc * 2 + kk) * 32;  // bytes
                uint32_t aH[4][4], aL[4][4];
#pragma unroll
                for (int i = 0; i < 4; i++) {
                    ldsm4(aH[i], aBaseH + i * (16 * A_PITCH) + aK);
                    ldsm4(aL[i], aBaseL + i * (16 * A_PITCH) + aK);
                }
                uint32_t bH[2][4], bL[2][4];
#pragma unroll
                for (int p = 0; p < 2; p++) {
                    uint32_t o = (uint32_t)p * (16 * B_PITCH) + (uint32_t)kk * 32;
                    ldsm4(bH[p], bBase + (s * 2 + 0) * B_SEG + o);
                    ldsm4(bL[p], bBase + (s * 2 + 1) * B_SEG + o);
                }
                // product-major ordering: no accumulator RAW chains
#pragma unroll
                for (int i = 0; i < 4; i++)
#pragma unroll
                    for (int j = 0; j < 4; j++)
                        mma_bf16(acc[i][j], aH[i], &bH[j >> 1][(j & 1) * 2]);
#pragma unroll
                for (int i = 0; i < 4; i++)
#pragma unroll
                    for (int j = 0; j < 4; j++)
                        mma_bf16(acc[i][j], aH[i], &bL[j >> 1][(j & 1) * 2]);
#pragma unroll
                for (int i = 0; i < 4; i++)
#pragma unroll
                    for (int j = 0; j < 4; j++)
                        mma_bf16(acc[i][j], aL[i], &bH[j >> 1][(j & 1) * 2]);
            }

            if (kc < 7) {
                __syncthreads();
                char* dh = gsm + SM_B + ((s ^ 1) * 2 + 0) * B_SEG +
                           lrow * B_PITCH + lseg * 16;
                char* dl = gsm + SM_B + ((s ^ 1) * 2 + 1) * B_SEG +
                           lrow * B_PITCH + lseg * 16;
                *(uint4*)dh = h0; *(uint4*)(dh + 16) = h1;
                *(uint4*)dl = l0; *(uint4*)(dl + 16) = l1;
                __syncthreads();
            }
        }

        // ---- Epilogue: add bias, store fp32 C ----
        const int rBase = m0 + warp_m * 64 + (lane >> 2);
        const int cBase = n0 + warp_n * 32 + (lane & 3) * 2;
#pragma unroll
        for (int j = 0; j < 4; j++) {
            const int col = cBase + j * 8;
            float bb0 = 0.f, bb1 = 0.f;
            if (b1) {
                bb0 = b1[col] + b2[col];
                bb1 = b1[col + 1] + b2[col + 1];
            }
#pragma unroll
            for (int i = 0; i < 4; i++) {
                const int row = rBase + i * 16;
                float2 v0 = make_float2(acc[i][j][0] + bb0, acc[i][j][1] + bb1);
                float2 v1 = make_float2(acc[i][j][2] + bb0, acc[i][j][3] + bb1);
                *(float2*)(C + (size_t)row * N + col) = v0;
                *(float2*)(C + (size_t)(row + 8) * N + col) = v1;
            }
        }
    }
}

// ---------------------------------------------------------------------------
// fp32 -> bf16 hi/lo split converter (weights + embedding table)
// ---------------------------------------------------------------------------
__global__ void conv_split(const float* __restrict__ src,
                           __nv_bfloat16* __restrict__ hi,
                           __nv_bfloat16* __restrict__ lo, int n)
{
    int i = blockIdx.x * 256 + threadIdx.x;
    if (i < n) {
        float v = src[i];
        __nv_bfloat16 h = __float2bfloat16(v);
        hi[i] = h;
        lo[i] = __float2bfloat16(v - __bfloat162float(h));
    }
}

// ---------------------------------------------------------------------------
// Recurrence: one CTA per batch row, 512 steps; W split regs/smem.
// Emits h as bf16 hi/lo (feeds GEMM A-operand directly).
// ---------------------------------------------------------------------------
#define WREG 48
#define WSMQ 16
#define WPITCH4 17

__device__ __forceinline__ float rnn_dot(
    const float4* __restrict__ wr, const float4* __restrict__ wsr,
    const float4* __restrict__ hb)
{
    float a0 = 0.f, a1 = 0.f, a2 = 0.f, a3 = 0.f;
#pragma unroll
    for (int q = 0; q < WREG; q++) {
        float4 h = hb[q];
        float4 w = wr[q];
        a0 = fmaf(w.x, h.x, a0);
        a1 = fmaf(w.y, h.y, a1);
        a2 = fmaf(w.z, h.z, a2);
        a3 = fmaf(w.w, h.w, a3);
    }
#pragma unroll
    for (int q = 0; q < WSMQ; q++) {
        float4 h = hb[WREG + q];
        float4 w = wsr[q];
        a0 = fmaf(w.x, h.x, a0);
        a1 = fmaf(w.y, h.y, a1);
        a2 = fmaf(w.z, h.z, a2);
        a3 = fmaf(w.w, h.w, a3);
    }
    return (a0 + a1) + (a2 + a3);
}

extern __shared__ float smem_r[];

__global__ void __launch_bounds__(256, 1) rnn_recur(
    const float* __restrict__ pre,        // [B][T][D]
    const float* __restrict__ Whh,        // [D][D]
    __nv_bfloat16* __restrict__ houtH,    // [B][T][D]
    __nv_bfloat16* __restrict__ houtL)
{
    float4* Wsm = (float4*)smem_r;
    float*  hA  = smem_r + 256 * WPITCH4 * 4;
    float*  hB  = hA + 256;

    int b = blockIdx.x;
    int j = threadIdx.x;

    float4 wr[WREG];
    {
        const float4* wrow = (const float4*)(Whh + (size_t)j * 256);
#pragma unroll
        for (int q = 0; q < WREG; q++) wr[q] = wrow[q];
    }
    for (int i = j; i < 256 * WSMQ; i += 256) {
        int r = i >> 4, c = i & 15;
        Wsm[r * WPITCH4 + c] =
            ((const float4*)(Whh + (size_t)r * 256 + WREG * 4))[c];
    }

    hA[j] = 0.f;
    __syncthreads();

    const float*   prow = pre   + ((size_t)b * Tn) * Dn;
    __nv_bfloat16* ohr  = houtH + ((size_t)b * Tn) * Dn;
    __nv_bfloat16* olr  = houtL + ((size_t)b * Tn) * Dn;
    const float4*  wsr  = Wsm + j * WPITCH4;

    float pcur = prow[j];

#pragma unroll 1
    for (int step = 0; step < Tn; step += 2) {
        {
            float pnext = prow[Dn + j];
            float s = rnn_dot(wr, wsr, (const float4*)hA);
            float v = tanhf(pcur + s);
            hB[j] = v;
            __nv_bfloat16 vh = __float2bfloat16(v);
            ohr[j] = vh;
            olr[j] = __float2bfloat16(v - __bfloat162float(vh));
            __syncthreads();
            pcur = pnext; prow += Dn; ohr += Dn; olr += Dn;
        }
        {
            float pnext = (step + 2 < Tn) ? prow[Dn + j] : 0.f;
            float s = rnn_dot(wr, wsr, (const float4*)hB);
            float v = tanhf(pcur + s);
            hA[j] = v;
            __nv_bfloat16 vh = __float2bfloat16(v);
            ohr[j] = vh;
            olr[j] = __float2bfloat16(v - __bfloat162float(vh));
            __syncthreads();
            pcur = pnext; prow += Dn; ohr += Dn; olr += Dn;
        }
    }
}

// ---------------------------------------------------------------------------
extern "C" void kernel_launch(void* const* d_in, const int* in_sizes, int n_in,
                              void* d_out, int out_size)
{
    (void)in_sizes; (void)n_in; (void)out_size;

    const int*   ids   = (const int*)  d_in[0];
    const float* emb   = (const float*)d_in[1];
    const float* Wih0  = (const float*)d_in[2];
    const float* Whh0  = (const float*)d_in[3];
    const float* bih0  = (const float*)d_in[4];
    const float* bhh0  = (const float*)d_in[5];
    const float* Wih1  = (const float*)d_in[6];
    const float* Whh1  = (const float*)d_in[7];
    const float* bih1  = (const float*)d_in[8];
    const float* bhh1  = (const float*)d_in[9];
    const float* Whead = (const float*)d_in[10];
    float* out = (float*)d_out;

    float *pre;           cudaGetSymbolAddress((void**)&pre,  g_pre);
    __nv_bfloat16 *hH;    cudaGetSymbolAddress((void**)&hH,   g_hH);
    __nv_bfloat16 *hL;    cudaGetSymbolAddress((void**)&hL,   g_hL);
    __nv_bfloat16 *embH;  cudaGetSymbolAddress((void**)&embH, g_embH);
    __nv_bfloat16 *embL;  cudaGetSymbolAddress((void**)&embL, g_embL);
    __nv_bfloat16 *w0H;   cudaGetSymbolAddress((void**)&w0H,  g_w0H);
    __nv_bfloat16 *w0L;   cudaGetSymbolAddress((void**)&w0L,  g_w0L);
    __nv_bfloat16 *w1H;   cudaGetSymbolAddress((void**)&w1H,  g_w1H);
    __nv_bfloat16 *w1L;   cudaGetSymbolAddress((void**)&w1L,  g_w1L);
    __nv_bfloat16 *whH;   cudaGetSymbolAddress((void**)&whH,  g_whH);
    __nv_bfloat16 *whL;   cudaGetSymbolAddress((void**)&whL,  g_whL);

    const int recur_smem = (256 * WPITCH4 * 4 + 512) * 4;   // 71680 B
    cudaFuncSetAttribute(rnn_recur, cudaFuncAttributeMaxDynamicSharedMemorySize,
                         recur_smem);
    cudaFuncSetAttribute(gemm_mma, cudaFuncAttributeMaxDynamicSharedMemorySize,
                         GEMM_SMEM);

    // Weight / embedding bf16 hi-lo splits
    conv_split<<<(Vn * Dn + 255) / 256, 256>>>(emb,   embH, embL, Vn * Dn);
    conv_split<<<(Dn * Dn + 255) / 256, 256>>>(Wih0,  w0H,  w0L,  Dn * Dn);
    conv_split<<<(Dn * Dn + 255) / 256, 256>>>(Wih1,  w1H,  w1L,  Dn * Dn);
    conv_split<<<(Sn * Dn + 255) / 256, 256>>>(Whead, whH,  whL,  Sn * Dn);

    const int M = Bn * Tn;   // 65536

    // pre0 = emb[ids] @ W_ih0^T + (b_ih0 + b_hh0)
    gemm_mma<<<M / 128, 256, GEMM_SMEM>>>(embH, embL, ids, w0H, w0L,
                                          bih0, bhh0, pre, Dn);
    // h1 recurrence (emits bf16 hi/lo)
    rnn_recur<<<Bn, 256, recur_smem>>>(pre, Whh0, hH, hL);
    // pre1 = h1 @ W_ih1^T + (b_ih1 + b_hh1)
    gemm_mma<<<M / 128, 256, GEMM_SMEM>>>(hH, hL, nullptr, w1H, w1L,
                                          bih1, bhh1, pre, Dn);
    // h2 recurrence
    rnn_recur<<<Bn, 256, recur_smem>>>(pre, Whh1, hH, hL);
    // logits = h2 @ W_head^T
    gemm_mma<<<M / 128, 256, GEMM_SMEM>>>(hH, hL, nullptr, whH, whL,
                                          nullptr, nullptr, out, Sn);
}